// round 6
// baseline (speedup 1.0000x reference)
#include <cuda_runtime.h>

// Problem constants
#define BB 4
#define TT 2048
#define NE 32
#define NH 8
#define NB 512                       // 4-row blocks per (b,h)
#define ROWS 32                      // rows per CTA
#define THR 256                      // 8 warps: warp = head, lane = row
#define NCTA 256                     // 64 CTAs per batch
#define SLICES 64                    // CTAs (= partial slices) per batch

// Cross-CTA state (zero-init at module load; reset by last-done CTA each run)
__device__ __align__(16) float g_part[BB][SLICES][128]; // bucketed partial sums
__device__ __align__(16) float g_GT[BB][NE][NE];        // G transposed: [o'][hc]
__device__ int g_arrive[BB];
__device__ int g_ready[BB];
__device__ int g_done[BB];

__device__ __forceinline__ float clip100(float v) {
    return fminf(fmaxf(v, -100.0f), 100.0f);
}

// ---- packed f32x2 helpers (sm_100+) ----
__device__ __forceinline__ unsigned long long pk2(float lo, float hi) {
    unsigned long long r;
    asm("mov.b64 %0, {%1, %2};" : "=l"(r) : "f"(lo), "f"(hi));
    return r;
}
__device__ __forceinline__ float hadd2(unsigned long long v) {
    float lo, hi;
    asm("mov.b64 {%0, %1}, %2;" : "=f"(lo), "=f"(hi) : "l"(v));
    return lo + hi;
}
__device__ __forceinline__ void fma2(unsigned long long& d,
                                     unsigned long long a, unsigned long long b) {
    asm("fma.rn.f32x2 %0, %1, %2, %0;" : "+l"(d) : "l"(a), "l"(b));
}
__device__ __forceinline__ void lds_v2u64(unsigned long long& a, unsigned long long& b,
                                          const void* p) {
    unsigned addr = (unsigned)__cvta_generic_to_shared(p);
    asm volatile("ld.shared.v2.u64 {%0, %1}, [%2];" : "=l"(a), "=l"(b) : "r"(addr));
}
__device__ __forceinline__ void ldg_v2u64(unsigned long long& a, unsigned long long& b,
                                          const void* p) {
    asm volatile("ld.global.v2.u64 {%0, %1}, [%2];" : "=l"(a), "=l"(b) : "l"(p));
}
__device__ __forceinline__ int ldcv(const int* p) {
    int v;
    asm volatile("ld.global.cv.b32 %0, [%1];" : "=r"(v) : "l"(p));
    return v;
}

__global__ __launch_bounds__(THR, 2) void fused_kernel(
    const float* __restrict__ x,
    const float* __restrict__ Wq, const float* __restrict__ bq,
    const float* __restrict__ Wv, const float* __restrict__ bv,
    const float* __restrict__ Wp, const float* __restrict__ bp,
    float* __restrict__ out)
{
    __shared__ __align__(16) float sWq[NE][NE];   // 128B rows, v2.u64 broadcasts
    __shared__ __align__(16) float sX[ROWS][36];  // x rows; reused for output
    __shared__ __align__(16) float sQ[ROWS][36];
    __shared__ __align__(16) float sP[ROWS][36];
    __shared__ float sWS[NE][33];                 // elected-CTA weight scratch
    __shared__ float sRed[2][128];                // elected-CTA reduce scratch
    __shared__ float sVb[4][NE];
    __shared__ float sbq[NE];
    __shared__ float sbp[NE];
    __shared__ int   sE;

    const int tid  = threadIdx.x;
    const int w    = tid >> 5;          // warp = head
    const int l    = tid & 31;          // lane = row
    const int tg0  = blockIdx.x * ROWS;
    const int b    = tg0 >> 11;         // 64 CTAs per batch
    const int slic = blockIdx.x & 63;

    // ================= Phase 0: stage Wq + x (vectorized) =================
    {
        const int ro = tid >> 3, cg = (tid & 7) * 4;
        *(float4*)&sWq[ro][cg] = ((const float4*)Wq)[tid];
        *(float4*)&sX[ro][cg]  = ((const float4*)(x + (size_t)tg0 * NE))[tid];
    }
    if (tid < NE)          sbq[tid]      = bq[tid];
    else if (tid < 2 * NE) sbp[tid - NE] = bp[tid - NE];
    __syncthreads();

    // ============ Phase 0b: bucketed partial sums -> publish ============
    if (tid < 128) {
        const int c = tid >> 5, e = tid & 31;
        float s = 0.0f;
        #pragma unroll
        for (int j = 0; j < 8; ++j) s += sX[4 * j + c][e];  // conflict-free
        g_part[b][slic][tid] = s;
    }
    __syncthreads();
    if (tid == 0) {
        __threadfence();
        const int old = atomicAdd(&g_arrive[b], 1);
        sE = (old == SLICES - 1);
    }
    __syncthreads();

    // ============ Elected CTA (last arriver): build G for batch ============
    if (sE) {
        __threadfence();   // acquire: see all partials
        {
            const int half = tid >> 7, bk = tid & 127;
            float s = 0.0f;
            #pragma unroll
            for (int t = 0; t < 32; ++t) s += g_part[b][half * 32 + t][bk];
            sRed[half][bk] = s;
        }
        {   // stage Wv (scalar into stride-33)
            const int ro = tid >> 3, cg = (tid & 7) * 4;
            const float4 v = ((const float4*)Wv)[tid];
            sWS[ro][cg] = v.x; sWS[ro][cg + 1] = v.y;
            sWS[ro][cg + 2] = v.z; sWS[ro][cg + 3] = v.w;
        }
        __syncthreads();
        if (tid < 128) {   // Vbar[c][o]
            const int c = tid >> 5, o = tid & 31;
            float acc = bv[o];
            #pragma unroll
            for (int e = 0; e < NE; ++e) {
                const float xb = (sRed[0][c * 32 + e] + sRed[1][c * 32 + e])
                                 * (1.0f / (float)NB);
                acc += xb * sWS[o][e];
            }
            sVb[c][o] = acc;
        }
        __syncthreads();
        {   // stage Wp
            const int ro = tid >> 3, cg = (tid & 7) * 4;
            const float4 v = ((const float4*)Wp)[tid];
            sWS[ro][cg] = v.x; sWS[ro][cg + 1] = v.y;
            sWS[ro][cg + 2] = v.z; sWS[ro][cg + 3] = v.w;
        }
        __syncthreads();
        #pragma unroll
        for (int i = 0; i < 4; ++i) {   // GT[o'][hc] = sum_d Vb[c][h4+d]*Wp[o'][h4+d]
            const int g  = i * THR + tid;
            const int hc = g >> 5, op = g & 31;
            const int h  = hc >> 2, c = hc & 3;
            float acc = 0.0f;
            #pragma unroll
            for (int d = 0; d < 4; ++d)
                acc += sVb[c][h * 4 + d] * sWS[op][h * 4 + d];
            g_GT[b][op][hc] = acc;
        }
        __syncthreads();
        if (tid == 0) {
            __threadfence();            // release G
            atomicExch(&g_ready[b], 1);
        }
    }

    // ================= Phase 1: q matvec (f32x2 packed) =================
    const int o0 = w * 4;
    {
        unsigned long long xr2[16];
        #pragma unroll
        for (int k = 0; k < 8; ++k)
            lds_v2u64(xr2[2 * k], xr2[2 * k + 1], &sX[l][4 * k]);  // conflict-free
        float qv[4];
        #pragma unroll
        for (int i = 0; i < 4; ++i) {
            const int o = o0 + i;                                  // warp-uniform
            unsigned long long acc = pk2(sbq[o], 0.0f);
            #pragma unroll
            for (int k = 0; k < 8; ++k) {
                unsigned long long w0, w1;
                lds_v2u64(w0, w1, &sWq[o][4 * k]);                 // broadcast
                fma2(acc, xr2[2 * k], w0);
                fma2(acc, xr2[2 * k + 1], w1);
            }
            qv[i] = clip100(hadd2(acc));
        }
        *(float4*)&sQ[l][o0] = make_float4(qv[0], qv[1], qv[2], qv[3]);
    }
    __syncwarp();   // RXTX reads only this warp's sQ columns

    // ================= Phase 2: RXTX + 4-way softmax =================
    {
        const int blk = l & ~3;
        const int rr  = l & 3;
        const float4 q0 = *(const float4*)&sQ[blk + 0][o0];
        const float4 q1 = *(const float4*)&sQ[blk + 1][o0];
        const float4 q2 = *(const float4*)&sQ[blk + 2][o0];
        const float4 q3 = *(const float4*)&sQ[blk + 3][o0];
        const float X1 = q0.x,  X2 = q0.y,  X3 = q0.z,  X4 = q0.w;
        const float X5 = q1.x,  X6 = q1.y,  X7 = q1.z,  X8 = q1.w;
        const float X9 = q2.x,  X10 = q2.y, X11 = q2.z, X12 = q2.w;
        const float X13 = q3.x, X14 = q3.y, X15 = q3.z, X16 = q3.w;

        const float m1  = (-X2 + X3 - X4 + X8) * (X8 + X11);
        const float m2  = (X1 - X5 - X6 + X7) * (X15 + X5);
        const float m3  = (-X2 + X12) * (-X10 + X16 + X12);
        const float m4  = (X9 - X6) * (X13 + X9 - X14);
        const float m5  = (X2 + X11) * (-X6 + X15 - X7);
        const float m6  = (X6 + X11) * (X6 + X7 - X11);
        const float m7  = X11 * (X6 + X7);
        const float m8  = X2 * (-X14 - X10 + X6 - X15 + X7 + X16 + X12);
        const float m9  = X6 * (X13 + X9 - X14 - X10 + X6 + X7 - X11);
        const float m10 = (X2 - X3 + X7 + X11 + X4 - X8) * X11;
        const float m11 = (X5 + X6 - X7) * X5;
        const float m12 = (X2 - X3 + X4) * X8;
        const float m13 = (-X1 + X5 + X6 + X3 - X7 + X11) * X15;
        const float m14 = (-X1 + X5 + X6) * (X13 + X9 + X15);
        const float m15 = (X2 + X4 - X8) * (X11 + X16 + X12);
        const float m16 = (X1 - X8) * (X9 - X16);
        const float m17 = X12 * (X10 - X12);
        const float m18 = X9 * (X13 - X14);
        const float m19 = (-X2 + X3) * (-X15 + X7 + X8);
        const float m20 = (X5 + X9 - X8) * X9;
        const float m21 = X8 * (X9 - X8 + X12);
        const float m22 = (-X6 + X7) * (X5 + X7 - X11);
        const float m23 = X1 * (X13 - X5 + X16);
        const float m24 = (-X1 + X4 + X12) * X16;
        const float m25 = (X9 + X2 + X10) * X14;
        const float m26 = (X6 + X10 + X12) * X10;

        const float z1 = m7 - m11 - m12;
        const float z2 = m1 + m12 + m21;
        const float z3 = m3 + m17 - m24;
        const float z4 = m2 + m11 + m23;
        const float z5 = m5 + m7 + m8;
        const float z6 = m4 - m18 - m20;
        const float z7 = m6 - m7 - m9;
        const float z8 = m17 + m18;

        const float c01 = m2 - m5 - z1 + m13 + m19;
        const float c02 = z2 + z3 + m15 + m16;
        const float c03 = z4 - z3 - z5 - m13;
        const float c11 = m1 + m6 - z1 + m10 + m22;
        const float c12 = z2 - z6 + z7 + m10;
        const float c13 = z4 + z6 + m14 + m16;
        const float c22 = m4 - z7 - z8 + m26;
        const float c23 = m3 + z5 + z8 + m25;

        float a0, a1, a2, a3;
        if      (rr == 0) { a0 = 0.0f; a1 = c01;  a2 = c02;  a3 = c03;  }
        else if (rr == 1) { a0 = c01;  a1 = c11;  a2 = c12;  a3 = c13;  }
        else if (rr == 2) { a0 = c02;  a1 = c12;  a2 = c22;  a3 = c23;  }
        else              { a0 = c03;  a1 = c13;  a2 = c23;  a3 = 0.0f; }

        a0 = clip100(a0) * 0.5f;
        a1 = clip100(a1) * 0.5f;
        a2 = clip100(a2) * 0.5f;
        a3 = clip100(a3) * 0.5f;

        const float mx = fmaxf(fmaxf(a0, a1), fmaxf(a2, a3));
        const float e0 = __expf(a0 - mx);
        const float e1 = __expf(a1 - mx);
        const float e2 = __expf(a2 - mx);
        const float e3 = __expf(a3 - mx);
        const float inv = 1.0f / (e0 + e1 + e2 + e3);

        *(float4*)&sP[l][o0] = make_float4(e0 * inv, e1 * inv, e2 * inv, e3 * inv);
    }
    __syncthreads();   // sP complete across warps

    // ================= Wait for G (brief; producer overlapped) =================
    if (tid == 0) {
        while (ldcv(&g_ready[b]) == 0) __nanosleep(64);
    }
    __syncthreads();
    __threadfence();   // acquire: order G reads after flag

    // ================= Phase 3: z = bp + P . G^T (f32x2 packed) =================
    {
        unsigned long long pr2[16];
        #pragma unroll
        for (int k = 0; k < 8; ++k)
            lds_v2u64(pr2[2 * k], pr2[2 * k + 1], &sP[l][4 * k]);
        float zv[4];
        #pragma unroll
        for (int i = 0; i < 4; ++i) {
            const int o = o0 + i;                              // warp-uniform
            const char* gp = (const char*)&g_GT[b][o][0];
            unsigned long long acc = pk2(sbp[o], 0.0f);
            #pragma unroll
            for (int k = 0; k < 8; ++k) {
                unsigned long long g0, g1;
                ldg_v2u64(g0, g1, gp + 16 * k);                // uniform -> L1 hit
                fma2(acc, pr2[2 * k], g0);
                fma2(acc, pr2[2 * k + 1], g1);
            }
            zv[i] = hadd2(acc);
        }
        *(float4*)&sX[l][o0] = make_float4(zv[0], zv[1], zv[2], zv[3]);
    }
    __syncthreads();

    // ================= Phase 4: vectorized store =================
    {
        const int ro = tid >> 3, cg = (tid & 7) * 4;
        ((float4*)(out + (size_t)tg0 * NE))[tid] = *(const float4*)&sX[ro][cg];
    }

    // ================= Epilogue: reset state for next replay =================
    if (tid == 0) {
        __threadfence();
        const int old = atomicAdd(&g_done[b], 1);
        if (old == SLICES - 1) {
            g_arrive[b] = 0;
            atomicExch(&g_ready[b], 0);
            g_done[b] = 0;
            __threadfence();
        }
    }
}

extern "C" void kernel_launch(void* const* d_in, const int* in_sizes, int n_in,
                              void* d_out, int out_size)
{
    // metadata order: x, Wq, bq, Wk, bk, Wv, bv, Wp, bp   (Wk/bk dead)
    const float* x  = (const float*)d_in[0];
    const float* Wq = (const float*)d_in[1];
    const float* bq = (const float*)d_in[2];
    const float* Wv = (const float*)d_in[5];
    const float* bv = (const float*)d_in[6];
    const float* Wp = (const float*)d_in[7];
    const float* bp = (const float*)d_in[8];
    float* out = (float*)d_out;

    fused_kernel<<<NCTA, THR>>>(x, Wq, bq, Wv, bv, Wp, bp, out);
}

// round 7
// speedup vs baseline: 1.4455x; 1.4455x over previous
#include <cuda_runtime.h>

// Problem constants
#define BB 4
#define TT 2048
#define NE 32
#define NH 8
#define NB 512                      // 4-row blocks per (b,h)
#define NSLICE 64                   // xpart slices per batch (32 rows each)
#define ROWS_B 32                   // kernel B rows per CTA
#define THR_B 256                   // 8 warps: warp = head, lane = row
#define NCTA_B ((BB * TT) / ROWS_B) // 256

// g_xpart[b][s][c*32+e] = sum over slice-s rows with (row%4==c) of x[row][e]
__device__ __align__(16) float g_xpart[BB][NSLICE][128];

__device__ __forceinline__ float clip100(float v) {
    return fminf(fmaxf(v, -100.0f), 100.0f);
}

// ---- packed f32x2 helpers (sm_100a) ----
__device__ __forceinline__ unsigned long long pk2(float lo, float hi) {
    unsigned long long r;
    asm("mov.b64 %0, {%1, %2};" : "=l"(r) : "f"(lo), "f"(hi));
    return r;
}
__device__ __forceinline__ float hadd2(unsigned long long v) {
    float lo, hi;
    asm("mov.b64 {%0, %1}, %2;" : "=f"(lo), "=f"(hi) : "l"(v));
    return lo + hi;
}
__device__ __forceinline__ void fma2(unsigned long long& d,
                                     unsigned long long a, unsigned long long b) {
    asm("fma.rn.f32x2 %0, %1, %2, %0;" : "+l"(d) : "l"(a), "l"(b));
}
__device__ __forceinline__ void lds_v2u64(unsigned long long& a, unsigned long long& b,
                                          const void* p) {
    unsigned addr = (unsigned)__cvta_generic_to_shared(p);
    asm volatile("ld.shared.v2.u64 {%0, %1}, [%2];" : "=l"(a), "=l"(b) : "r"(addr));
}

// -------- Kernel A: partial column sums of x, bucketed by (row % 4) --------
__global__ __launch_bounds__(128) void xpart_kernel(const float* __restrict__ x)
{
    const int b   = blockIdx.x >> 6;
    const int s   = blockIdx.x & 63;
    const int tid = threadIdx.x;

    const float* xs0 = x + ((size_t)b * TT + (size_t)s * 32) * NE;
    float acc = 0.0f;
    #pragma unroll
    for (int j = 0; j < 8; ++j) acc += xs0[j * 128 + tid];
    g_xpart[b][s][tid] = acc;
}

// -------- Kernel B: fused Vbar/G + q, RXTX, softmax, z = bp + P.G^T --------
// 256 threads = 8 warps (w = head) x 32 lanes (l = row).
__global__ __launch_bounds__(THR_B, 2) void rxtx_attn_kernel(
    const float* __restrict__ x,
    const float* __restrict__ Wq, const float* __restrict__ bq,
    const float* __restrict__ Wv, const float* __restrict__ bv,
    const float* __restrict__ Wp, const float* __restrict__ bp,
    float* __restrict__ out)
{
    __shared__ __align__(16) float sWq[NE][NE];   // 128B rows; v2.u64 broadcasts
    __shared__ float sWv[NE][33];                  // per-lane rows, scalar
    __shared__ float sWp[NE][33];                  // per-lane rows, scalar
    __shared__ __align__(16) float sGT[NE][36];   // G transposed; v2.u64 broadcasts
    __shared__ float sbq[NE];
    __shared__ float sbp[NE];
    __shared__ __align__(16) float sXh8[8][128];  // xpart partials per slice-group
    __shared__ float sVb[4][NE];
    __shared__ __align__(16) float sX[ROWS_B][36]; // x rows
    __shared__ __align__(16) float sQ[ROWS_B][36]; // q (float4 access)
    __shared__ __align__(16) float sP[ROWS_B][36]; // softmax probs

    const int tid = threadIdx.x;
    const int w   = tid >> 5;           // warp = head
    const int l   = tid & 31;           // lane = row
    const int tg0 = blockIdx.x * ROWS_B;
    const int b   = tg0 >> 11;          // 64 CTAs per batch, aligned

    // ================= Phase 0: stage everything (vectorized) =================
    {
        const int ro = tid >> 3, cg = (tid & 7) * 4;    // 256 float4s cover 32x32
        *(float4*)&sWq[ro][cg] = ((const float4*)Wq)[tid];
        const float4 wv = ((const float4*)Wv)[tid];
        sWv[ro][cg + 0] = wv.x; sWv[ro][cg + 1] = wv.y;
        sWv[ro][cg + 2] = wv.z; sWv[ro][cg + 3] = wv.w;
        const float4 wp = ((const float4*)Wp)[tid];
        sWp[ro][cg + 0] = wp.x; sWp[ro][cg + 1] = wp.y;
        sWp[ro][cg + 2] = wp.z; sWp[ro][cg + 3] = wp.w;
        *(float4*)&sX[ro][cg] = ((const float4*)(x + (size_t)tg0 * NE))[tid];
    }
    if (tid < NE)          sbq[tid]      = bq[tid];
    else if (tid < 2 * NE) sbp[tid - NE] = bp[tid - NE];

    // xpart partial reduce: warp w sums its 8 slices, float4 per lane
    {
        const int fb = l * 4;
        float4 ps = make_float4(0.f, 0.f, 0.f, 0.f);
        #pragma unroll
        for (int s = 0; s < 8; ++s) {
            const float4 v = *(const float4*)&g_xpart[b][w * 8 + s][fb];
            ps.x += v.x; ps.y += v.y; ps.z += v.z; ps.w += v.w;
        }
        *(float4*)&sXh8[w][fb] = ps;
    }
    __syncthreads();

    // ========== Phase 1: q matvec (f32x2, all warps) + Vbar (warps 0-3) ==========
    const int o0 = w * 4;
    {
        unsigned long long xr2[16];
        #pragma unroll
        for (int k = 0; k < 8; ++k)
            lds_v2u64(xr2[2 * k], xr2[2 * k + 1], &sX[l][4 * k]);  // conflict-free
        float qv[4];
        #pragma unroll
        for (int i = 0; i < 4; ++i) {
            const int o = o0 + i;                                  // warp-uniform
            unsigned long long acc = pk2(sbq[o], 0.0f);
            #pragma unroll
            for (int k = 0; k < 8; ++k) {
                unsigned long long w0, w1;
                lds_v2u64(w0, w1, &sWq[o][4 * k]);                 // broadcast
                fma2(acc, xr2[2 * k], w0);
                fma2(acc, xr2[2 * k + 1], w1);
            }
            qv[i] = clip100(hadd2(acc));
        }
        *(float4*)&sQ[l][o0] = make_float4(qv[0], qv[1], qv[2], qv[3]);
    }
    if (w < 4) {                                        // Vbar: warp = c, lane = e/o
        const int c = w;
        float xb = 0.0f;
        #pragma unroll
        for (int sg = 0; sg < 8; ++sg) xb += sXh8[sg][c * 32 + l];
        xb *= (1.0f / (float)NB);
        float acc = bv[l];
        #pragma unroll
        for (int e = 0; e < NE; ++e)
            acc += __shfl_sync(0xffffffffu, xb, e) * sWv[l][e];
        sVb[c][l] = acc;
    }
    __syncwarp();   // RXTX only needs this warp's sQ columns

    // ================= Phase 2: RXTX + 4-way softmax =================
    {
        const int blk = l & ~3;
        const int rr  = l & 3;
        const float4 q0 = *(const float4*)&sQ[blk + 0][o0];
        const float4 q1 = *(const float4*)&sQ[blk + 1][o0];
        const float4 q2 = *(const float4*)&sQ[blk + 2][o0];
        const float4 q3 = *(const float4*)&sQ[blk + 3][o0];
        const float X1 = q0.x,  X2 = q0.y,  X3 = q0.z,  X4 = q0.w;
        const float X5 = q1.x,  X6 = q1.y,  X7 = q1.z,  X8 = q1.w;
        const float X9 = q2.x,  X10 = q2.y, X11 = q2.z, X12 = q2.w;
        const float X13 = q3.x, X14 = q3.y, X15 = q3.z, X16 = q3.w;

        const float m1  = (-X2 + X3 - X4 + X8) * (X8 + X11);
        const float m2  = (X1 - X5 - X6 + X7) * (X15 + X5);
        const float m3  = (-X2 + X12) * (-X10 + X16 + X12);
        const float m4  = (X9 - X6) * (X13 + X9 - X14);
        const float m5  = (X2 + X11) * (-X6 + X15 - X7);
        const float m6  = (X6 + X11) * (X6 + X7 - X11);
        const float m7  = X11 * (X6 + X7);
        const float m8  = X2 * (-X14 - X10 + X6 - X15 + X7 + X16 + X12);
        const float m9  = X6 * (X13 + X9 - X14 - X10 + X6 + X7 - X11);
        const float m10 = (X2 - X3 + X7 + X11 + X4 - X8) * X11;
        const float m11 = (X5 + X6 - X7) * X5;
        const float m12 = (X2 - X3 + X4) * X8;
        const float m13 = (-X1 + X5 + X6 + X3 - X7 + X11) * X15;
        const float m14 = (-X1 + X5 + X6) * (X13 + X9 + X15);
        const float m15 = (X2 + X4 - X8) * (X11 + X16 + X12);
        const float m16 = (X1 - X8) * (X9 - X16);
        const float m17 = X12 * (X10 - X12);
        const float m18 = X9 * (X13 - X14);
        const float m19 = (-X2 + X3) * (-X15 + X7 + X8);
        const float m20 = (X5 + X9 - X8) * X9;
        const float m21 = X8 * (X9 - X8 + X12);
        const float m22 = (-X6 + X7) * (X5 + X7 - X11);
        const float m23 = X1 * (X13 - X5 + X16);
        const float m24 = (-X1 + X4 + X12) * X16;
        const float m25 = (X9 + X2 + X10) * X14;
        const float m26 = (X6 + X10 + X12) * X10;

        const float z1 = m7 - m11 - m12;
        const float z2 = m1 + m12 + m21;
        const float z3 = m3 + m17 - m24;
        const float z4 = m2 + m11 + m23;
        const float z5 = m5 + m7 + m8;
        const float z6 = m4 - m18 - m20;
        const float z7 = m6 - m7 - m9;
        const float z8 = m17 + m18;

        const float c01 = m2 - m5 - z1 + m13 + m19;
        const float c02 = z2 + z3 + m15 + m16;
        const float c03 = z4 - z3 - z5 - m13;
        const float c11 = m1 + m6 - z1 + m10 + m22;
        const float c12 = z2 - z6 + z7 + m10;
        const float c13 = z4 + z6 + m14 + m16;
        const float c22 = m4 - z7 - z8 + m26;
        const float c23 = m3 + z5 + z8 + m25;

        float a0, a1, a2, a3;
        if      (rr == 0) { a0 = 0.0f; a1 = c01;  a2 = c02;  a3 = c03;  }
        else if (rr == 1) { a0 = c01;  a1 = c11;  a2 = c12;  a3 = c13;  }
        else if (rr == 2) { a0 = c02;  a1 = c12;  a2 = c22;  a3 = c23;  }
        else              { a0 = c03;  a1 = c13;  a2 = c23;  a3 = 0.0f; }

        a0 = clip100(a0) * 0.5f;
        a1 = clip100(a1) * 0.5f;
        a2 = clip100(a2) * 0.5f;
        a3 = clip100(a3) * 0.5f;

        const float mx = fmaxf(fmaxf(a0, a1), fmaxf(a2, a3));
        const float e0 = __expf(a0 - mx);
        const float e1 = __expf(a1 - mx);
        const float e2 = __expf(a2 - mx);
        const float e3 = __expf(a3 - mx);
        const float inv = 1.0f / (e0 + e1 + e2 + e3);

        *(float4*)&sP[l][o0] = make_float4(e0 * inv, e1 * inv, e2 * inv, e3 * inv);
    }
    __syncthreads();   // covers sVb (warps 0-3) and sP (all warps)

    // ========== Phase 2b: G build, stored TRANSPOSED: sGT[o'][hc] ==========
    #pragma unroll
    for (int i = 0; i < 4; ++i) {
        const int g  = i * THR_B + tid;   // 0..1023
        const int hc = g >> 5;            // warp-uniform per i
        const int op = g & 31;            // per-lane
        const int h  = hc >> 2;
        const int c  = hc & 3;
        float acc = 0.0f;
        #pragma unroll
        for (int d = 0; d < 4; ++d)
            acc += sVb[c][h * 4 + d] * sWp[op][h * 4 + d];
        sGT[op][hc] = acc;
    }
    __syncthreads();

    // ========== Phase 3: z = bp + P . G^T (f32x2) + direct store ==========
    {
        unsigned long long pr2[16];
        #pragma unroll
        for (int k = 0; k < 8; ++k)
            lds_v2u64(pr2[2 * k], pr2[2 * k + 1], &sP[l][4 * k]);
        float zv[4];
        #pragma unroll
        for (int i = 0; i < 4; ++i) {
            const int o = o0 + i;                        // warp-uniform
            unsigned long long acc = pk2(sbp[o], 0.0f);
            #pragma unroll
            for (int k = 0; k < 8; ++k) {
                unsigned long long g0, g1;
                lds_v2u64(g0, g1, &sGT[o][4 * k]);       // broadcast
                fma2(acc, pr2[2 * k], g0);
                fma2(acc, pr2[2 * k + 1], g1);
            }
            zv[i] = hadd2(acc);
        }
        // direct 16B store: row tg0+l, cols [o0, o0+4)
        *(float4*)(out + ((size_t)(tg0 + l)) * NE + o0) =
            make_float4(zv[0], zv[1], zv[2], zv[3]);
    }
}

extern "C" void kernel_launch(void* const* d_in, const int* in_sizes, int n_in,
                              void* d_out, int out_size)
{
    // metadata order: x, Wq, bq, Wk, bk, Wv, bv, Wp, bp   (Wk/bk dead)
    const float* x  = (const float*)d_in[0];
    const float* Wq = (const float*)d_in[1];
    const float* bq = (const float*)d_in[2];
    const float* Wv = (const float*)d_in[5];
    const float* bv = (const float*)d_in[6];
    const float* Wp = (const float*)d_in[7];
    const float* bp = (const float*)d_in[8];
    float* out = (float*)d_out;

    xpart_kernel<<<BB * NSLICE, 128>>>(x);
    rxtx_attn_kernel<<<NCTA_B, THR_B>>>(x, Wq, bq, Wv, bv, Wp, bp, out);
}